// round 1
// baseline (speedup 1.0000x reference)
#include <cuda_runtime.h>
#include <math.h>

#define D_IN 1024
#define NHEAD 16
#define NHID 64
#define BATCH 2
#define SEQ 2048
#define MTOT (BATCH * SEQ)    /* 4096 */
#define NTOT (NHEAD * NHID)   /* 1024 */

// Scratch for projected Q/K/V in (B, H, S, Dh) layout. 16 MB each.
__device__ float g_Q[(size_t)BATCH * NHEAD * SEQ * NHID];
__device__ float g_K[(size_t)BATCH * NHEAD * SEQ * NHID];
__device__ float g_V[(size_t)BATCH * NHEAD * SEQ * NHID];

// ---------------------------------------------------------------------------
// GEMM: out = X @ W^T + bias, scattered into (B,H,S,Dh) scratch.
// X: (MTOT, D_IN) row-major. W: (NTOT, D_IN) row-major. Both K-major -> "NT".
// BM=BN=128, BK=16, 256 threads, 8x8 register tile.
// ---------------------------------------------------------------------------
template <int WHICH>
__global__ __launch_bounds__(256) void qkv_gemm(const float* __restrict__ X,
                                                const float* __restrict__ W,
                                                const float* __restrict__ bias)
{
    __shared__ float As[16][132];
    __shared__ float Bs[16][132];

    const int tid = threadIdx.x;
    const int bm = blockIdx.y * 128;
    const int bn = blockIdx.x * 128;

    const int lr = tid >> 2;          // 0..63
    const int lc = (tid & 3) << 2;    // 0,4,8,12
    const float* Ap = X + (size_t)(bm + lr) * D_IN + lc;
    const float* Bp = W + (size_t)(bn + lr) * D_IN + lc;

    const int ty = tid >> 4;          // 0..15
    const int tx = tid & 15;          // 0..15

    float acc[8][8];
#pragma unroll
    for (int i = 0; i < 8; i++)
#pragma unroll
        for (int j = 0; j < 8; j++) acc[i][j] = 0.0f;

    for (int k0 = 0; k0 < D_IN; k0 += 16) {
        float4 a0 = *(const float4*)(Ap + k0);
        float4 a1 = *(const float4*)(Ap + (size_t)64 * D_IN + k0);
        float4 b0 = *(const float4*)(Bp + k0);
        float4 b1 = *(const float4*)(Bp + (size_t)64 * D_IN + k0);

        As[lc + 0][lr] = a0.x; As[lc + 1][lr] = a0.y;
        As[lc + 2][lr] = a0.z; As[lc + 3][lr] = a0.w;
        As[lc + 0][lr + 64] = a1.x; As[lc + 1][lr + 64] = a1.y;
        As[lc + 2][lr + 64] = a1.z; As[lc + 3][lr + 64] = a1.w;

        Bs[lc + 0][lr] = b0.x; Bs[lc + 1][lr] = b0.y;
        Bs[lc + 2][lr] = b0.z; Bs[lc + 3][lr] = b0.w;
        Bs[lc + 0][lr + 64] = b1.x; Bs[lc + 1][lr + 64] = b1.y;
        Bs[lc + 2][lr + 64] = b1.z; Bs[lc + 3][lr + 64] = b1.w;

        __syncthreads();

#pragma unroll
        for (int k = 0; k < 16; k++) {
            float ar[8], br[8];
            *(float4*)&ar[0] = *(const float4*)&As[k][ty * 8];
            *(float4*)&ar[4] = *(const float4*)&As[k][ty * 8 + 4];
            *(float4*)&br[0] = *(const float4*)&Bs[k][tx * 8];
            *(float4*)&br[4] = *(const float4*)&Bs[k][tx * 8 + 4];
#pragma unroll
            for (int i = 0; i < 8; i++)
#pragma unroll
                for (int j = 0; j < 8; j++) acc[i][j] += ar[i] * br[j];
        }
        __syncthreads();
    }

    // Epilogue: add bias, scatter to (B,H,S,Dh).
    float* dst = (WHICH == 0) ? g_Q : (WHICH == 1) ? g_K : g_V;
    const int nbase = bn + tx * 8;
    const int h = nbase >> 6;
    const int d = nbase & 63;
    float bb[8];
#pragma unroll
    for (int j = 0; j < 8; j++) bb[j] = bias[nbase + j];

#pragma unroll
    for (int i = 0; i < 8; i++) {
        const int m = bm + ty * 8 + i;
        const int b = m >> 11;          // / SEQ
        const int s = m & (SEQ - 1);
        float* o = dst + (((size_t)(b * NHEAD + h) * SEQ + s) * NHID + d);
        float4 v0 = make_float4(acc[i][0] + bb[0], acc[i][1] + bb[1],
                                acc[i][2] + bb[2], acc[i][3] + bb[3]);
        float4 v1 = make_float4(acc[i][4] + bb[4], acc[i][5] + bb[5],
                                acc[i][6] + bb[6], acc[i][7] + bb[7]);
        *(float4*)o = v0;
        *(float4*)(o + 4) = v1;
    }
}

// ---------------------------------------------------------------------------
// Flash attention, fp32. One block = 128 queries of one (b,h).
// 256 threads: ty=tid/16 owns 8 q rows, tx=tid%16 owns 4 k cols / 4 d cols.
// smem: Qs[128][64] + Kt[64][64] (d-major) + Vs[64][64] + Ps[128][64] = 96 KB.
// ---------------------------------------------------------------------------
__global__ __launch_bounds__(256, 2) void attn_kernel(float* __restrict__ out)
{
    extern __shared__ float sm[];
    float* Qs = sm;                    // [128][64]
    float* Kt = sm + 128 * 64;         // [64][64], layout [d][j]
    float* Vs = Kt + 64 * 64;          // [64][64], layout [k][d]
    float* Ps = Vs + 64 * 64;          // [128][64], layout [q][k]

    const int tid = threadIdx.x;
    const int ty = tid >> 4;           // 0..15
    const int tx = tid & 15;           // 0..15
    const int bh = blockIdx.y;         // b*16 + h
    const int q0 = blockIdx.x * 128;

    const float* Qg = g_Q + (size_t)bh * SEQ * NHID;
    const float* Kg = g_K + (size_t)bh * SEQ * NHID;
    const float* Vg = g_V + (size_t)bh * SEQ * NHID;

    // Load Q tile, pre-scaled by 1/sqrt(Dh) = 0.125.
    {
        const int r = tid >> 1;            // 0..127
        const int c = (tid & 1) * 32;
        const float4* src = (const float4*)(Qg + (size_t)(q0 + r) * NHID + c);
        float4* dq = (float4*)(Qs + r * 64 + c);
#pragma unroll
        for (int i = 0; i < 8; i++) {
            float4 v = src[i];
            v.x *= 0.125f; v.y *= 0.125f; v.z *= 0.125f; v.w *= 0.125f;
            dq[i] = v;
        }
    }

    float m_i[8], l_i[8], O[8][4];
#pragma unroll
    for (int a = 0; a < 8; a++) {
        m_i[a] = -INFINITY;
        l_i[a] = 0.0f;
#pragma unroll
        for (int c = 0; c < 4; c++) O[a][c] = 0.0f;
    }

    for (int kv = 0; kv < SEQ; kv += 64) {
        __syncthreads();   // previous PV done with Vs/Ps; Q load visible (1st iter)

        // Load K tile transposed (Kt[d][j]) and V tile direct (Vs[k][d]).
        {
            const int j = tid >> 2;              // 0..63
            const int dk = (tid & 3) * 16;       // 0,16,32,48
            const float4* ks = (const float4*)(Kg + (size_t)(kv + j) * NHID + dk);
#pragma unroll
            for (int i = 0; i < 4; i++) {
                float4 v = ks[i];
                const int dd = dk + i * 4;
                Kt[(dd + 0) * 64 + j] = v.x;
                Kt[(dd + 1) * 64 + j] = v.y;
                Kt[(dd + 2) * 64 + j] = v.z;
                Kt[(dd + 3) * 64 + j] = v.w;
            }
            const float4* vsrc = (const float4*)(Vg + (size_t)(kv + j) * NHID + dk);
            float4* vdst = (float4*)(Vs + j * 64 + dk);
#pragma unroll
            for (int i = 0; i < 4; i++) vdst[i] = vsrc[i];
        }
        __syncthreads();

        // S = Qs @ K^T for this tile (scores already scaled via Q).
        float s[8][4];
#pragma unroll
        for (int a = 0; a < 8; a++)
#pragma unroll
            for (int b = 0; b < 4; b++) s[a][b] = 0.0f;

#pragma unroll
        for (int d = 0; d < 64; d += 4) {
            float4 k4[4];
#pragma unroll
            for (int dd = 0; dd < 4; dd++)
                k4[dd] = *(const float4*)&Kt[(d + dd) * 64 + tx * 4];
#pragma unroll
            for (int a = 0; a < 8; a++) {
                const float4 q4 = *(const float4*)&Qs[(ty * 8 + a) * 64 + d];
                s[a][0] += q4.x * k4[0].x + q4.y * k4[1].x + q4.z * k4[2].x + q4.w * k4[3].x;
                s[a][1] += q4.x * k4[0].y + q4.y * k4[1].y + q4.z * k4[2].y + q4.w * k4[3].y;
                s[a][2] += q4.x * k4[0].z + q4.y * k4[1].z + q4.z * k4[2].z + q4.w * k4[3].z;
                s[a][3] += q4.x * k4[0].w + q4.y * k4[1].w + q4.z * k4[2].w + q4.w * k4[3].w;
            }
        }

        // Online softmax update + stage P to smem.
#pragma unroll
        for (int a = 0; a < 8; a++) {
            float rm = fmaxf(fmaxf(s[a][0], s[a][1]), fmaxf(s[a][2], s[a][3]));
#pragma unroll
            for (int off = 8; off >= 1; off >>= 1)
                rm = fmaxf(rm, __shfl_xor_sync(0xffffffffu, rm, off));
            const float mn = fmaxf(m_i[a], rm);
            const float corr = __expf(m_i[a] - mn);
            m_i[a] = mn;
            float rs = 0.0f;
#pragma unroll
            for (int b = 0; b < 4; b++) {
                s[a][b] = __expf(s[a][b] - mn);
                rs += s[a][b];
            }
#pragma unroll
            for (int off = 8; off >= 1; off >>= 1)
                rs += __shfl_xor_sync(0xffffffffu, rs, off);
            l_i[a] = l_i[a] * corr + rs;
#pragma unroll
            for (int c = 0; c < 4; c++) O[a][c] *= corr;
            *(float4*)&Ps[(ty * 8 + a) * 64 + tx * 4] =
                make_float4(s[a][0], s[a][1], s[a][2], s[a][3]);
        }
        __syncthreads();

        // O += P @ V
#pragma unroll
        for (int k = 0; k < 64; k += 4) {
            float4 v4[4];
#pragma unroll
            for (int kk = 0; kk < 4; kk++)
                v4[kk] = *(const float4*)&Vs[(k + kk) * 64 + tx * 4];
#pragma unroll
            for (int a = 0; a < 8; a++) {
                const float4 p4 = *(const float4*)&Ps[(ty * 8 + a) * 64 + k];
                O[a][0] += p4.x * v4[0].x + p4.y * v4[1].x + p4.z * v4[2].x + p4.w * v4[3].x;
                O[a][1] += p4.x * v4[0].y + p4.y * v4[1].y + p4.z * v4[2].y + p4.w * v4[3].y;
                O[a][2] += p4.x * v4[0].z + p4.y * v4[1].z + p4.z * v4[2].z + p4.w * v4[3].z;
                O[a][3] += p4.x * v4[0].w + p4.y * v4[1].w + p4.z * v4[2].w + p4.w * v4[3].w;
            }
        }
    }

    // Epilogue: normalize and write (B, S, H*Dh).
    const int b = bh >> 4;
    const int h = bh & 15;
#pragma unroll
    for (int a = 0; a < 8; a++) {
        const float inv = 1.0f / l_i[a];
        const int qg = q0 + ty * 8 + a;
        float* o = out + ((size_t)(b * SEQ + qg) * NTOT) + h * NHID + tx * 4;
        *(float4*)o = make_float4(O[a][0] * inv, O[a][1] * inv,
                                  O[a][2] * inv, O[a][3] * inv);
    }
}

// ---------------------------------------------------------------------------
extern "C" void kernel_launch(void* const* d_in, const int* in_sizes, int n_in,
                              void* d_out, int out_size)
{
    const float* xq = (const float*)d_in[0];
    const float* xk = (const float*)d_in[1];
    const float* xv = (const float*)d_in[2];
    const float* wq = (const float*)d_in[3];
    const float* bq = (const float*)d_in[4];
    const float* wk = (const float*)d_in[5];
    const float* bk = (const float*)d_in[6];
    const float* wv = (const float*)d_in[7];
    const float* bv = (const float*)d_in[8];
    float* out = (float*)d_out;

    dim3 gg(NTOT / 128, MTOT / 128);
    qkv_gemm<0><<<gg, 256>>>(xq, wq, bq);
    qkv_gemm<1><<<gg, 256>>>(xk, wk, bk);
    qkv_gemm<2><<<gg, 256>>>(xv, wv, bv);

    const int attn_smem = 96 * 1024;
    cudaFuncSetAttribute(attn_kernel, cudaFuncAttributeMaxDynamicSharedMemorySize,
                         attn_smem);
    dim3 ga(SEQ / 128, BATCH * NHEAD);
    attn_kernel<<<ga, 256, attn_smem>>>(out);
}

// round 4
// speedup vs baseline: 2.9312x; 2.9312x over previous
#include <cuda_runtime.h>
#include <math.h>
#include <stdint.h>

#define D_IN 1024
#define NHEAD 16
#define NHID 64
#define BATCH 2
#define SEQ 2048
#define MTOT (BATCH * SEQ)   /* 4096 */
#define NTOT (NHEAD * NHID)  /* 1024 */

// Q/K/V scratch in (B,H,S,Dh) layout, values pre-rounded to tf32 (Q pre-scaled by 0.125).
__device__ float g_Q[(size_t)BATCH * NHEAD * SEQ * NHID];
__device__ float g_K[(size_t)BATCH * NHEAD * SEQ * NHID];
__device__ float g_V[(size_t)BATCH * NHEAD * SEQ * NHID];

// ---------------------------------------------------------------------------
// helpers
// ---------------------------------------------------------------------------
__device__ __forceinline__ uint32_t f2tf(float x) {
    uint32_t r;
    asm volatile("cvt.rna.tf32.f32 %0, %1;" : "=r"(r) : "f"(x));
    return r;
}

__device__ __forceinline__ void mma_tf32(float* d, const uint32_t* a, const uint32_t* b) {
    asm volatile(
        "mma.sync.aligned.m16n8k8.row.col.f32.tf32.tf32.f32 "
        "{%0,%1,%2,%3}, {%4,%5,%6,%7}, {%8,%9}, {%0,%1,%2,%3};\n"
        : "+f"(d[0]), "+f"(d[1]), "+f"(d[2]), "+f"(d[3])
        : "r"(a[0]), "r"(a[1]), "r"(a[2]), "r"(a[3]), "r"(b[0]), "r"(b[1]));
}

__device__ __forceinline__ void cp_async16(uint32_t dst, const void* src) {
    asm volatile("cp.async.cg.shared.global [%0], [%1], 16;\n" :: "r"(dst), "l"(src));
}
__device__ __forceinline__ void cp_commit() {
    asm volatile("cp.async.commit_group;\n");
}
template <int N>
__device__ __forceinline__ void cp_wait() {
    asm volatile("cp.async.wait_group %0;\n" :: "n"(N));
}

// ---------------------------------------------------------------------------
// Fused QKV GEMM (tf32 tensor cores): out = X @ W^T + bias -> g_{Q,K,V}.
// Block 128x128, Ktile 32, 8 warps (warp tile 32m x 64n), double-buffered cp.async.
// smem ld = 36 floats (36 mod 32 == 4 -> conflict-free fragment loads).
// ---------------------------------------------------------------------------
#define G_LD 36
#define G_BUF (128 * G_LD)
#define GEMM_SMEM_BYTES (4 * G_BUF * 4)  /* As[2]+Bs[2] */

__device__ __forceinline__ void gemm_issue(const float* Asrc, const float* Bsrc,
                                           uint32_t aDst, uint32_t bDst, int kt) {
    const int buf = kt & 1;
    const float* as = Asrc + kt * 32;
    const float* bs = Bsrc + kt * 32;
    const uint32_t ad = aDst + buf * (G_BUF * 4);
    const uint32_t bd = bDst + buf * (G_BUF * 4);
#pragma unroll
    for (int j = 0; j < 4; j++) {
        cp_async16(ad + j * 16, as + j * 4);
        cp_async16(bd + j * 16, bs + j * 4);
    }
    cp_commit();
}

__global__ __launch_bounds__(256) void qkv_gemm_tc(
    const float* __restrict__ xq, const float* __restrict__ xk, const float* __restrict__ xv,
    const float* __restrict__ wq, const float* __restrict__ bq,
    const float* __restrict__ wk, const float* __restrict__ bk,
    const float* __restrict__ wv, const float* __restrict__ bv)
{
    extern __shared__ float smg[];
    float* As = smg;                 // [2][128][36]
    float* Bs = smg + 2 * G_BUF;     // [2][128][36]

    const int z = blockIdx.z;
    const float* X    = (z == 0) ? xq : (z == 1) ? xk : xv;
    const float* W    = (z == 0) ? wq : (z == 1) ? wk : wv;
    const float* bias = (z == 0) ? bq : (z == 1) ? bk : bv;
    float* dst        = (z == 0) ? g_Q : (z == 1) ? g_K : g_V;

    const int tid = threadIdx.x;
    const int bm = blockIdx.y * 128;
    const int bn = blockIdx.x * 128;
    const int warp = tid >> 5, lane = tid & 31;
    const int g = lane >> 2, t = lane & 3;
    const int wm = (warp >> 1) * 32;
    const int wn = (warp & 1) * 64;

    const int lrow = tid >> 1;
    const int lhalf = (tid & 1) * 16;
    const float* Asrc = X + (size_t)(bm + lrow) * D_IN + lhalf;
    const float* Bsrc = W + (size_t)(bn + lrow) * D_IN + lhalf;
    const uint32_t aDst = (uint32_t)__cvta_generic_to_shared(As + lrow * G_LD + lhalf);
    const uint32_t bDst = (uint32_t)__cvta_generic_to_shared(Bs + lrow * G_LD + lhalf);

    float acc[2][8][4];
#pragma unroll
    for (int mt = 0; mt < 2; mt++)
#pragma unroll
        for (int j = 0; j < 8; j++)
#pragma unroll
            for (int c = 0; c < 4; c++) acc[mt][j][c] = 0.0f;

    gemm_issue(Asrc, Bsrc, aDst, bDst, 0);
    gemm_issue(Asrc, Bsrc, aDst, bDst, 1);

    const int NKT = D_IN / 32;  // 32
    for (int kt = 0; kt < NKT; kt++) {
        if (kt == NKT - 1) cp_wait<0>(); else cp_wait<1>();
        __syncthreads();
        const float* Ab = As + (kt & 1) * G_BUF;
        const float* Bb = Bs + (kt & 1) * G_BUF;
#pragma unroll
        for (int ks = 0; ks < 4; ks++) {
            const int k0 = ks * 8;
            uint32_t af[2][4], bf[8][2];
#pragma unroll
            for (int mt = 0; mt < 2; mt++) {
                const float* p = Ab + (wm + mt * 16 + g) * G_LD + k0 + t;
                af[mt][0] = f2tf(p[0]);
                af[mt][1] = f2tf(p[8 * G_LD]);
                af[mt][2] = f2tf(p[4]);
                af[mt][3] = f2tf(p[8 * G_LD + 4]);
            }
#pragma unroll
            for (int j = 0; j < 8; j++) {
                const float* p = Bb + (wn + j * 8 + g) * G_LD + k0 + t;
                bf[j][0] = f2tf(p[0]);
                bf[j][1] = f2tf(p[4]);
            }
#pragma unroll
            for (int mt = 0; mt < 2; mt++)
#pragma unroll
                for (int j = 0; j < 8; j++)
                    mma_tf32(acc[mt][j], af[mt], bf[j]);
        }
        __syncthreads();
        if (kt + 2 < NKT) gemm_issue(Asrc, Bsrc, aDst, bDst, kt + 2);
    }

    // Epilogue: +bias, (Q only) *0.125, round to tf32, scatter to (B,H,S,Dh).
    const float scale = (z == 0) ? 0.125f : 1.0f;
#pragma unroll
    for (int mt = 0; mt < 2; mt++) {
#pragma unroll
        for (int half = 0; half < 2; half++) {
            const int m = bm + wm + mt * 16 + half * 8 + g;
            const int b = m >> 11;
            const int s = m & (SEQ - 1);
#pragma unroll
            for (int j = 0; j < 8; j++) {
                const int n = bn + wn + j * 8 + 2 * t;
                const int h = n >> 6, d = n & 63;
                float v0 = (acc[mt][j][half * 2 + 0] + bias[n])     * scale;
                float v1 = (acc[mt][j][half * 2 + 1] + bias[n + 1]) * scale;
                float2 o = make_float2(__uint_as_float(f2tf(v0)),
                                       __uint_as_float(f2tf(v1)));
                *(float2*)(dst + (((size_t)(b * NHEAD + h) * SEQ + s) * NHID + d)) = o;
            }
        }
    }
}

// ---------------------------------------------------------------------------
// Flash attention on tf32 tensor cores. BQ=256, BKV=64, 8 warps (32q x 64kv).
// smem ld = 68 (68 mod 32 == 4). K/V double-buffered via cp.async.
// Q/K/V already tf32-rounded (and Q pre-scaled) by the GEMM epilogue.
// ---------------------------------------------------------------------------
#define A_LD 68
#define A_QROWS 256
#define A_KVBUF (64 * A_LD)
#define ATT_SMEM_FLOATS (A_QROWS * A_LD + 2 * A_KVBUF + 2 * A_KVBUF + A_QROWS * A_LD)
#define ATT_SMEM_BYTES (ATT_SMEM_FLOATS * 4)  /* 208,896 */

// Load one 64-row x 64-float K tile and V tile (16B chunks; 16 chunks per row).
__device__ __forceinline__ void attn_issue_kv(const float* Kg, const float* Vg,
                                              uint32_t kBase, uint32_t vBase,
                                              int tid, int it) {
    const int buf = it & 1;
    const int kv0 = it * 64;
#pragma unroll
    for (int i = 0; i < 4; i++) {
        const int c = tid + 256 * i;         // 0..1023 chunks of 16B
        const int row = c >> 4;              // 16 chunks per 64-float row
        const int off = (c & 15) * 4;        // float offset within row
        cp_async16(kBase + (buf * A_KVBUF + row * A_LD + off) * 4,
                   Kg + (size_t)(kv0 + row) * NHID + off);
        cp_async16(vBase + (buf * A_KVBUF + row * A_LD + off) * 4,
                   Vg + (size_t)(kv0 + row) * NHID + off);
    }
    cp_commit();
}

__global__ __launch_bounds__(256, 1) void attn_tc(float* __restrict__ out)
{
    extern __shared__ float sma[];
    float* Qs = sma;                         // [256][68]
    float* Ks = Qs + A_QROWS * A_LD;         // [2][64][68]
    float* Vs = Ks + 2 * A_KVBUF;            // [2][64][68]
    float* Ps = Vs + 2 * A_KVBUF;            // [256][68]

    const int tid = threadIdx.x;
    const int warp = tid >> 5, lane = tid & 31;
    const int g = lane >> 2, t = lane & 3;
    const int bh = blockIdx.y;
    const int q0 = blockIdx.x * A_QROWS;
    const int wq = warp * 32;

    const float* Qg = g_Q + (size_t)bh * SEQ * NHID + (size_t)q0 * NHID;
    const float* Kg = g_K + (size_t)bh * SEQ * NHID;
    const float* Vg = g_V + (size_t)bh * SEQ * NHID;

    // Load Q tile: 256 rows x 64 floats = 4096 16B chunks (16 per row).
    {
        const uint32_t qb = (uint32_t)__cvta_generic_to_shared(Qs);
#pragma unroll
        for (int i = 0; i < 16; i++) {
            const int c = tid + 256 * i;      // 0..4095
            const int row = c >> 4;
            const int off = (c & 15) * 4;
            cp_async16(qb + (row * A_LD + off) * 4, Qg + (size_t)row * NHID + off);
        }
    }
    const uint32_t kBase = (uint32_t)__cvta_generic_to_shared(Ks);
    const uint32_t vBase = (uint32_t)__cvta_generic_to_shared(Vs);
    attn_issue_kv(Kg, Vg, kBase, vBase, tid, 0);   // commits group 0 (Q + KV0)
    attn_issue_kv(Kg, Vg, kBase, vBase, tid, 1);   // group 1

    float m_i[4], l_i[4], O[2][8][4];
#pragma unroll
    for (int r = 0; r < 4; r++) { m_i[r] = -INFINITY; l_i[r] = 0.0f; }
#pragma unroll
    for (int mt = 0; mt < 2; mt++)
#pragma unroll
        for (int j = 0; j < 8; j++)
#pragma unroll
            for (int c = 0; c < 4; c++) O[mt][j][c] = 0.0f;

    const int NIT = SEQ / 64;  // 32
    for (int it = 0; it < NIT; it++) {
        if (it == NIT - 1) cp_wait<0>(); else cp_wait<1>();
        __syncthreads();
        const float* Kb = Ks + (it & 1) * A_KVBUF;
        const float* Vb = Vs + (it & 1) * A_KVBUF;

        // ---- S = Q @ K^T (scores; Q pre-scaled) ----
        float S[2][8][4];
#pragma unroll
        for (int mt = 0; mt < 2; mt++)
#pragma unroll
            for (int j = 0; j < 8; j++)
#pragma unroll
                for (int c = 0; c < 4; c++) S[mt][j][c] = 0.0f;

#pragma unroll
        for (int ks = 0; ks < 8; ks++) {
            const int k0 = ks * 8;
            uint32_t af[2][4], bf[8][2];
#pragma unroll
            for (int mt = 0; mt < 2; mt++) {
                const float* p = Qs + (wq + mt * 16 + g) * A_LD + k0 + t;
                af[mt][0] = __float_as_uint(p[0]);
                af[mt][1] = __float_as_uint(p[8 * A_LD]);
                af[mt][2] = __float_as_uint(p[4]);
                af[mt][3] = __float_as_uint(p[8 * A_LD + 4]);
            }
#pragma unroll
            for (int j = 0; j < 8; j++) {
                const float* p = Kb + (j * 8 + g) * A_LD + k0 + t;
                bf[j][0] = __float_as_uint(p[0]);
                bf[j][1] = __float_as_uint(p[4]);
            }
#pragma unroll
            for (int mt = 0; mt < 2; mt++)
#pragma unroll
                for (int j = 0; j < 8; j++)
                    mma_tf32(S[mt][j], af[mt], bf[j]);
        }

        // ---- online softmax (rows owned by quads; shfl over t) ----
#pragma unroll
        for (int mt = 0; mt < 2; mt++) {
#pragma unroll
            for (int half = 0; half < 2; half++) {
                const int ri = mt * 2 + half;
                float mx = -INFINITY;
#pragma unroll
                for (int j = 0; j < 8; j++)
                    mx = fmaxf(mx, fmaxf(S[mt][j][half * 2], S[mt][j][half * 2 + 1]));
                mx = fmaxf(mx, __shfl_xor_sync(0xffffffffu, mx, 1));
                mx = fmaxf(mx, __shfl_xor_sync(0xffffffffu, mx, 2));
                const float mn = fmaxf(m_i[ri], mx);
                const float corr = __expf(m_i[ri] - mn);
                m_i[ri] = mn;
                float rs = 0.0f;
#pragma unroll
                for (int j = 0; j < 8; j++) {
                    const float e0 = __expf(S[mt][j][half * 2]     - mn);
                    const float e1 = __expf(S[mt][j][half * 2 + 1] - mn);
                    S[mt][j][half * 2]     = e0;
                    S[mt][j][half * 2 + 1] = e1;
                    rs += e0 + e1;
                }
                rs += __shfl_xor_sync(0xffffffffu, rs, 1);
                rs += __shfl_xor_sync(0xffffffffu, rs, 2);
                l_i[ri] = l_i[ri] * corr + rs;
#pragma unroll
                for (int j = 0; j < 8; j++) {
                    O[mt][j][half * 2]     *= corr;
                    O[mt][j][half * 2 + 1] *= corr;
                }
            }
        }

        // ---- stage P (tf32-rounded) to warp-private smem rows ----
#pragma unroll
        for (int mt = 0; mt < 2; mt++)
#pragma unroll
            for (int half = 0; half < 2; half++) {
                float* pr = Ps + (wq + mt * 16 + half * 8 + g) * A_LD;
#pragma unroll
                for (int j = 0; j < 8; j++) {
                    float2 v = make_float2(
                        __uint_as_float(f2tf(S[mt][j][half * 2])),
                        __uint_as_float(f2tf(S[mt][j][half * 2 + 1])));
                    *(float2*)(pr + j * 8 + 2 * t) = v;
                }
            }
        __syncwarp();

        // ---- O += P @ V ----
#pragma unroll
        for (int ks = 0; ks < 8; ks++) {
            const int k0 = ks * 8;
            uint32_t af[2][4], bf[8][2];
#pragma unroll
            for (int mt = 0; mt < 2; mt++) {
                const float* p = Ps + (wq + mt * 16 + g) * A_LD + k0 + t;
                af[mt][0] = __float_as_uint(p[0]);
                af[mt][1] = __float_as_uint(p[8 * A_LD]);
                af[mt][2] = __float_as_uint(p[4]);
                af[mt][3] = __float_as_uint(p[8 * A_LD + 4]);
            }
#pragma unroll
            for (int j = 0; j < 8; j++) {
                const float* p = Vb + (k0 + t) * A_LD + j * 8 + g;
                bf[j][0] = __float_as_uint(p[0]);
                bf[j][1] = __float_as_uint(p[4 * A_LD]);
            }
#pragma unroll
            for (int mt = 0; mt < 2; mt++)
#pragma unroll
                for (int j = 0; j < 8; j++)
                    mma_tf32(O[mt][j], af[mt], bf[j]);
        }

        __syncthreads();
        if (it + 2 < NIT) attn_issue_kv(Kg, Vg, kBase, vBase, tid, it + 2);
    }

    // Epilogue: normalize, write (B, S, H*Dh).
    const int b = bh >> 4, h = bh & 15;
#pragma unroll
    for (int mt = 0; mt < 2; mt++)
#pragma unroll
        for (int half = 0; half < 2; half++) {
            const int ri = mt * 2 + half;
            const float inv = 1.0f / l_i[ri];
            const int q = q0 + wq + mt * 16 + half * 8 + g;
            float* orow = out + (size_t)(b * SEQ + q) * NTOT + h * NHID;
#pragma unroll
            for (int j = 0; j < 8; j++) {
                float2 v = make_float2(O[mt][j][half * 2] * inv,
                                       O[mt][j][half * 2 + 1] * inv);
                *(float2*)(orow + j * 8 + 2 * t) = v;
            }
        }
}

// ---------------------------------------------------------------------------
extern "C" void kernel_launch(void* const* d_in, const int* in_sizes, int n_in,
                              void* d_out, int out_size)
{
    const float* xq = (const float*)d_in[0];
    const float* xk = (const float*)d_in[1];
    const float* xv = (const float*)d_in[2];
    const float* wq = (const float*)d_in[3];
    const float* bq = (const float*)d_in[4];
    const float* wk = (const float*)d_in[5];
    const float* bk = (const float*)d_in[6];
    const float* wv = (const float*)d_in[7];
    const float* bv = (const float*)d_in[8];
    float* out = (float*)d_out;

    cudaFuncSetAttribute(qkv_gemm_tc, cudaFuncAttributeMaxDynamicSharedMemorySize,
                         GEMM_SMEM_BYTES);
    cudaFuncSetAttribute(attn_tc, cudaFuncAttributeMaxDynamicSharedMemorySize,
                         ATT_SMEM_BYTES);

    dim3 gg(NTOT / 128, MTOT / 128, 3);
    qkv_gemm_tc<<<gg, 256, GEMM_SMEM_BYTES>>>(xq, xk, xv, wq, bq, wk, bk, wv, bv);

    dim3 ga(SEQ / A_QROWS, BATCH * NHEAD);
    attn_tc<<<ga, 256, ATT_SMEM_BYTES>>>(out);
}